// round 1
// baseline (speedup 1.0000x reference)
#include <cuda_runtime.h>
#include <math.h>

#define BB 32
#define LL 4096
#define CC 256
#define VV 5

// ---------------- device scratch (no allocations allowed) ----------------
__device__ float g_base[BB * CC];            // sum over L of features (pre-divide)
__device__ float g_A1[BB * VV * CC];         // sum_l a*rs*(f-m)
__device__ float g_A3[BB * VV];              // sum_l a  (== attn_sum before EPS)
__device__ float g_projg[BB * CC * VV];      // g_in[c]*scale*proj[c,v]
__device__ float g_sgp[BB * VV];             // sum_c g_in*scale*proj
__device__ float g_sbp[BB * VV];             // sum_c b_in*scale*proj
__device__ float g_MT[CC * CC];              // MT[e][c] = sum_k Wk[e,k]*Wq[c,k]

// ---------------- zero scratch ----------------
__global__ void kz() {
    int idx = blockIdx.x * 256 + threadIdx.x;      // grid 160 -> 40960 threads
    if (idx < BB * CC)      g_base[idx] = 0.f;
    if (idx < BB * VV * CC) g_A1[idx]   = 0.f;
    if (idx < BB * VV)      g_A3[idx]   = 0.f;
}

// ---------------- MT = Wk @ Wq^T (runs once per launch) ----------------
__global__ void km(const float* __restrict__ Wq, const float* __restrict__ Wk) {
    __shared__ float As[32][33];  // Wk tile  [e][k]
    __shared__ float Bs[32][33];  // Wq tile  [c][k]
    int tx = threadIdx.x & 31, ty = threadIdx.x >> 5;   // ty 0..7
    int c0 = blockIdx.x * 32, e0 = blockIdx.y * 32;
    float acc[4] = {0.f, 0.f, 0.f, 0.f};
    for (int k0 = 0; k0 < CC; k0 += 32) {
#pragma unroll
        for (int j = 0; j < 4; j++) {
            As[ty + 8 * j][tx] = Wk[(e0 + ty + 8 * j) * CC + k0 + tx];
            Bs[ty + 8 * j][tx] = Wq[(c0 + ty + 8 * j) * CC + k0 + tx];
        }
        __syncthreads();
#pragma unroll
        for (int kk = 0; kk < 32; kk++) {
            float bq = Bs[tx][kk];
#pragma unroll
            for (int j = 0; j < 4; j++) acc[j] += As[ty + 8 * j][kk] * bq;
        }
        __syncthreads();
    }
#pragma unroll
    for (int j = 0; j < 4; j++)
        g_MT[(e0 + ty + 8 * j) * CC + c0 + tx] = acc[j];
}

// ---------------- per-batch mean of features over L ----------------
__global__ void kmean(const float* __restrict__ F) {
    int b = blockIdx.y, t = threadIdx.x;
    int l0 = blockIdx.x * 128;
    const float* p = F + ((size_t)b * LL + l0) * CC + t;
    float s0 = 0.f, s1 = 0.f, s2 = 0.f, s3 = 0.f;
#pragma unroll 4
    for (int l = 0; l < 128; l += 4) {
        s0 += p[(l + 0) * CC];
        s1 += p[(l + 1) * CC];
        s2 += p[(l + 2) * CC];
        s3 += p[(l + 3) * CC];
    }
    atomicAdd(&g_base[b * CC + t], (s0 + s1) + (s2 + s3));
}

// ---------------- the big fused streaming pass ----------------
// One warp handles 32 tokens; lane owns columns {4*lane..4*lane+3, 128+4*lane..+3}.
// Per token: LN stats + 5 logit dots in one read, softmax over V=5,
// accumulate A1 += a*rs*(f-m) in registers, RED to global at the end.
__global__ void __launch_bounds__(128) kbig(const float* __restrict__ F,
                                            float* __restrict__ attn_out,
                                            int write_attn) {
    int b = blockIdx.y;
    int w = threadIdx.x >> 5, lane = threadIdx.x & 31;
    int l0 = blockIdx.x * 128 + w * 32;

    int cA = 4 * lane;          // f[0..3]
    int cB = 128 + 4 * lane;    // f[4..7]

    float gp[VV][8], sgp[VV], sbp[VV];
#pragma unroll
    for (int v = 0; v < VV; v++) {
        sgp[v] = g_sgp[b * VV + v];
        sbp[v] = g_sbp[b * VV + v];
#pragma unroll
        for (int i = 0; i < 8; i++) {
            int c = (i < 4) ? (cA + i) : (cB + (i - 4));
            gp[v][i] = g_projg[(b * CC + c) * VV + v];
        }
    }
    float A1[VV][8], A3[VV];
#pragma unroll
    for (int v = 0; v < VV; v++) {
        A3[v] = 0.f;
#pragma unroll
        for (int i = 0; i < 8; i++) A1[v][i] = 0.f;
    }

    const float4* base = (const float4*)(F + ((size_t)b * LL + l0) * CC);

    for (int r = 0; r < 32; r++) {
        float4 fa = base[r * 64 + lane];
        float4 fb = base[r * 64 + lane + 32];
        float f[8] = {fa.x, fa.y, fa.z, fa.w, fb.x, fb.y, fb.z, fb.w};

        float s = 0.f, s2 = 0.f, d[VV] = {0.f, 0.f, 0.f, 0.f, 0.f};
#pragma unroll
        for (int i = 0; i < 8; i++) {
            float fv = f[i];
            s += fv;
            s2 += fv * fv;
#pragma unroll
            for (int v = 0; v < VV; v++) d[v] += fv * gp[v][i];
        }
#pragma unroll
        for (int off = 16; off; off >>= 1) {
            s  += __shfl_xor_sync(0xffffffffu, s, off);
            s2 += __shfl_xor_sync(0xffffffffu, s2, off);
#pragma unroll
            for (int v = 0; v < VV; v++) d[v] += __shfl_xor_sync(0xffffffffu, d[v], off);
        }
        float m = s * (1.0f / 256.0f);
        float var = s2 * (1.0f / 256.0f) - m * m;
        float rs = rsqrtf(var + 1e-5f);

        float lg[VV];
#pragma unroll
        for (int v = 0; v < VV; v++) lg[v] = rs * (d[v] - m * sgp[v]) + sbp[v];
        float mx = lg[0];
#pragma unroll
        for (int v = 1; v < VV; v++) mx = fmaxf(mx, lg[v]);
        float e[VV], se = 0.f;
#pragma unroll
        for (int v = 0; v < VV; v++) { e[v] = __expf(lg[v] - mx); se += e[v]; }
        float inv = 1.0f / se;
        float a[VV];
#pragma unroll
        for (int v = 0; v < VV; v++) a[v] = e[v] * inv;

#pragma unroll
        for (int i = 0; i < 8; i++) f[i] -= m;
#pragma unroll
        for (int v = 0; v < VV; v++) {
            float cf = a[v] * rs;
            A3[v] += a[v];
#pragma unroll
            for (int i = 0; i < 8; i++) A1[v][i] += cf * f[i];
        }

        if (write_attn && lane < VV) {
            float av = lane == 0 ? a[0] : lane == 1 ? a[1] : lane == 2 ? a[2]
                     : lane == 3 ? a[3] : a[4];
            attn_out[((size_t)b * LL + l0 + r) * VV + lane] = av;
        }
    }

#pragma unroll
    for (int v = 0; v < VV; v++) {
#pragma unroll
        for (int i = 0; i < 8; i++) {
            int c = (i < 4) ? (cA + i) : (cB + (i - 4));
            atomicAdd(&g_A1[(b * VV + v) * CC + c], A1[v][i]);
        }
        if (lane == 0) atomicAdd(&g_A3[b * VV + v], A3[v]);
    }
}

// ---------------- per-batch slot update + projection for next iteration ----------------
// grid = 32 (one block per batch), 512 threads.
__global__ void __launch_bounds__(512) kslot(
    float* __restrict__ slots_g,             // lives in d_out
    const float* __restrict__ noise,
    const float* __restrict__ g_in_p, const float* __restrict__ b_in_p,
    const float* __restrict__ g_sl,   const float* __restrict__ b_sl,
    const float* __restrict__ g_up,   const float* __restrict__ b_up,
    const float* __restrict__ Wv,
    const float* __restrict__ W1, const float* __restrict__ b1,
    const float* __restrict__ W2, const float* __restrict__ b2,
    const float* __restrict__ scale_p, const float* __restrict__ ns_p,
    int do_init, int do_update, int do_proj)
{
    __shared__ float sSlots[VV][CC];
    __shared__ float sA[VV][CC];       // S (attn^T x) then slots_norm (reused)
    __shared__ float sU[VV][CC];
    __shared__ float sH[VV][CC];
    __shared__ float sHid[VV][2 * CC];
    __shared__ float a3s[VV];
    __shared__ float sred[2 * VV];

    int b = blockIdx.x, t = threadIdx.x;
    int wid = t >> 5, lane = t & 31;

    if (do_init) {
        float ns = fabsf(ns_p[0]);
        for (int idx = t; idx < VV * CC; idx += 512) {
            int v = idx >> 8, c = idx & 255;
            float s = g_base[b * CC + c] * (1.0f / (float)LL)
                    + noise[(b * VV + v) * CC + c] * ns;
            sSlots[v][c] = s;
            slots_g[(b * VV + v) * CC + c] = s;
        }
    } else {
        for (int idx = t; idx < VV * CC; idx += 512) {
            int v = idx >> 8, c = idx & 255;
            sSlots[v][c] = slots_g[(b * VV + v) * CC + c];
        }
    }
    __syncthreads();

    if (do_update) {
        if (t < VV) { a3s[t] = g_A3[b * VV + t]; g_A3[b * VV + t] = 0.f; }
        __syncthreads();
        for (int idx = t; idx < VV * CC; idx += 512) {
            int v = idx >> 8, c = idx & 255;
            int gi = (b * VV + v) * CC + c;
            float a1 = g_A1[gi];
            g_A1[gi] = 0.f;
            sA[v][c] = g_in_p[c] * a1 + b_in_p[c] * a3s[v];
        }
        __syncthreads();
        if (t < CC) {
            float acc[VV] = {0.f, 0.f, 0.f, 0.f, 0.f};
            for (int c2 = 0; c2 < CC; c2++) {
                float wv = Wv[c2 * CC + t];
#pragma unroll
                for (int v = 0; v < VV; v++) acc[v] += sA[v][c2] * wv;
            }
#pragma unroll
            for (int v = 0; v < VV; v++) sU[v][t] = acc[v] / (a3s[v] + 1e-8f);
        }
        __syncthreads();
        if (wid < VV) {   // LayerNorm of updates, one warp per slot
            int v = wid;
            float uv[8], s = 0.f, s2 = 0.f;
#pragma unroll
            for (int i = 0; i < 8; i++) {
                uv[i] = sU[v][lane + 32 * i];
                s += uv[i]; s2 += uv[i] * uv[i];
            }
#pragma unroll
            for (int off = 16; off; off >>= 1) {
                s  += __shfl_xor_sync(0xffffffffu, s, off);
                s2 += __shfl_xor_sync(0xffffffffu, s2, off);
            }
            float m = s * (1.0f / 256.0f);
            float var = s2 * (1.0f / 256.0f) - m * m;
            float rs = rsqrtf(var + 1e-5f);
#pragma unroll
            for (int i = 0; i < 8; i++) {
                int c = lane + 32 * i;
                sH[v][c] = (uv[i] - m) * rs * g_up[c] + b_up[c];
            }
        }
        __syncthreads();
        {   // hidden = relu(h @ W1 + b1), j = t (512 outputs), W1 read once/block
            float acc[VV];
#pragma unroll
            for (int v = 0; v < VV; v++) acc[v] = b1[t];
            for (int c = 0; c < CC; c++) {
                float w = W1[c * (2 * CC) + t];
#pragma unroll
                for (int v = 0; v < VV; v++) acc[v] += sH[v][c] * w;
            }
#pragma unroll
            for (int v = 0; v < VV; v++) sHid[v][t] = fmaxf(acc[v], 0.f);
        }
        __syncthreads();
        if (t < CC) {  // delta = hid @ W2 + b2; slots += delta
            float acc[VV];
#pragma unroll
            for (int v = 0; v < VV; v++) acc[v] = b2[t];
            for (int j = 0; j < 2 * CC; j++) {
                float w = W2[j * CC + t];
#pragma unroll
                for (int v = 0; v < VV; v++) acc[v] += sHid[v][j] * w;
            }
#pragma unroll
            for (int v = 0; v < VV; v++) {
                float sv = sSlots[v][t] + acc[v];
                sSlots[v][t] = sv;
                slots_g[(b * VV + v) * CC + t] = sv;
            }
        }
        __syncthreads();
    }

    if (do_proj) {
        if (t < 2 * VV) sred[t] = 0.f;
        if (wid < VV) {   // LN(slots) with g_slots/b_slots -> sA
            int v = wid;
            float uv[8], s = 0.f, s2 = 0.f;
#pragma unroll
            for (int i = 0; i < 8; i++) {
                uv[i] = sSlots[v][lane + 32 * i];
                s += uv[i]; s2 += uv[i] * uv[i];
            }
#pragma unroll
            for (int off = 16; off; off >>= 1) {
                s  += __shfl_xor_sync(0xffffffffu, s, off);
                s2 += __shfl_xor_sync(0xffffffffu, s2, off);
            }
            float m = s * (1.0f / 256.0f);
            float var = s2 * (1.0f / 256.0f) - m * m;
            float rs = rsqrtf(var + 1e-5f);
#pragma unroll
            for (int i = 0; i < 8; i++) {
                int c = lane + 32 * i;
                sA[v][c] = (uv[i] - m) * rs * g_sl[c] + b_sl[c];
            }
        }
        __syncthreads();
        if (t < CC) {
            float acc[VV] = {0.f, 0.f, 0.f, 0.f, 0.f};
            for (int e = 0; e < CC; e++) {
                float mc = g_MT[e * CC + t];
#pragma unroll
                for (int v = 0; v < VV; v++) acc[v] += mc * sA[v][e];
            }
            float sc = scale_p[0];
            float gi_c = g_in_p[t], bi_c = b_in_p[t];
            float cg[VV], cb[VV];
#pragma unroll
            for (int v = 0; v < VV; v++) {
                float pr = acc[v] * sc;
                float gpv = gi_c * pr;
                g_projg[(b * CC + t) * VV + v] = gpv;
                cg[v] = gpv;
                cb[v] = bi_c * pr;
            }
#pragma unroll
            for (int off = 16; off; off >>= 1) {
#pragma unroll
                for (int v = 0; v < VV; v++) {
                    cg[v] += __shfl_xor_sync(0xffffffffu, cg[v], off);
                    cb[v] += __shfl_xor_sync(0xffffffffu, cb[v], off);
                }
            }
            if (lane == 0) {
#pragma unroll
                for (int v = 0; v < VV; v++) {
                    atomicAdd(&sred[v], cg[v]);
                    atomicAdd(&sred[VV + v], cb[v]);
                }
            }
        }
        __syncthreads();
        if (t < VV) {
            g_sgp[b * VV + t] = sred[t];
            g_sbp[b * VV + t] = sred[VV + t];
        }
    }
}

extern "C" void kernel_launch(void* const* d_in, const int* in_sizes, int n_in,
                              void* d_out, int out_size) {
    const float* F     = (const float*)d_in[0];
    const float* noise = (const float*)d_in[1];
    const float* Wq    = (const float*)d_in[2];
    const float* Wk    = (const float*)d_in[3];
    const float* Wv    = (const float*)d_in[4];
    const float* scale = (const float*)d_in[5];
    const float* g_in  = (const float*)d_in[6];
    const float* b_in  = (const float*)d_in[7];
    const float* g_sl  = (const float*)d_in[8];
    const float* b_sl  = (const float*)d_in[9];
    const float* g_up  = (const float*)d_in[10];
    const float* b_up  = (const float*)d_in[11];
    const float* W1    = (const float*)d_in[12];
    const float* b1    = (const float*)d_in[13];
    const float* W2    = (const float*)d_in[14];
    const float* b2    = (const float*)d_in[15];
    const float* nsc   = (const float*)d_in[16];

    float* out       = (float*)d_out;
    float* slots_out = out;                     // [B,V,C] = 40960 floats
    float* attn_out  = out + BB * VV * CC;      // [B,L,V] = 655360 floats

    kz<<<160, 256>>>();
    km<<<dim3(8, 8), 256>>>(Wq, Wk);
    kmean<<<dim3(32, 32), 256>>>(F);

    // iter 1: init slots + proj
    kslot<<<32, 512>>>(slots_out, noise, g_in, b_in, g_sl, b_sl, g_up, b_up,
                       Wv, W1, b1, W2, b2, scale, nsc, 1, 0, 1);
    kbig<<<dim3(32, 32), 128>>>(F, attn_out, 0);
    // iter 2: update + proj
    kslot<<<32, 512>>>(slots_out, noise, g_in, b_in, g_sl, b_sl, g_up, b_up,
                       Wv, W1, b1, W2, b2, scale, nsc, 0, 1, 1);
    kbig<<<dim3(32, 32), 128>>>(F, attn_out, 0);
    // iter 3: update + proj, last big pass writes attn
    kslot<<<32, 512>>>(slots_out, noise, g_in, b_in, g_sl, b_sl, g_up, b_up,
                       Wv, W1, b1, W2, b2, scale, nsc, 0, 1, 1);
    kbig<<<dim3(32, 32), 128>>>(F, attn_out, 1);
    // final slot update (no proj needed)
    kslot<<<32, 512>>>(slots_out, noise, g_in, b_in, g_sl, b_sl, g_up, b_up,
                       Wv, W1, b1, W2, b2, scale, nsc, 0, 1, 0);
}

// round 2
// speedup vs baseline: 1.1968x; 1.1968x over previous
#include <cuda_runtime.h>
#include <math.h>

#define BB 32
#define LL 4096
#define CC 256
#define VV 5

// ---------------- device scratch (no allocations allowed) ----------------
__device__ float g_base[BB * CC];            // sum over L of features (pre-divide)
__device__ float g_A1[BB * VV * CC];         // sum_l a*rs*(f-m)
__device__ float g_A3[BB * VV];              // sum_l a  (== attn_sum before EPS)
__device__ float g_projg[BB * VV * CC];      // [b][v][c] = g_in[c]*scale*proj[c,v]
__device__ float g_sgp[BB * VV];             // sum_c g_in*scale*proj
__device__ float g_sbp[BB * VV];             // sum_c b_in*scale*proj
__device__ float g_MT[CC * CC];              // MT[e][c] = sum_k Wk[e,k]*Wq[c,k]

// ---------------- MT = Wk @ Wq^T, also zero g_base ----------------
__global__ void km(const float* __restrict__ Wq, const float* __restrict__ Wk) {
    __shared__ float As[32][33];  // Wk tile  [e][k]
    __shared__ float Bs[32][33];  // Wq tile  [c][k]
    int tx = threadIdx.x & 31, ty = threadIdx.x >> 5;   // ty 0..7
    int c0 = blockIdx.x * 32, e0 = blockIdx.y * 32;

    int flat = (blockIdx.y * 8 + blockIdx.x) * 256 + threadIdx.x;
    if (flat < BB * CC) g_base[flat] = 0.f;

    float acc[4] = {0.f, 0.f, 0.f, 0.f};
    for (int k0 = 0; k0 < CC; k0 += 32) {
#pragma unroll
        for (int j = 0; j < 4; j++) {
            As[ty + 8 * j][tx] = Wk[(e0 + ty + 8 * j) * CC + k0 + tx];
            Bs[ty + 8 * j][tx] = Wq[(c0 + ty + 8 * j) * CC + k0 + tx];
        }
        __syncthreads();
#pragma unroll
        for (int kk = 0; kk < 32; kk++) {
            float bq = Bs[tx][kk];
#pragma unroll
            for (int j = 0; j < 4; j++) acc[j] += As[ty + 8 * j][kk] * bq;
        }
        __syncthreads();
    }
#pragma unroll
    for (int j = 0; j < 4; j++)
        g_MT[(e0 + ty + 8 * j) * CC + c0 + tx] = acc[j];
}

// ---------------- per-batch mean of features; x-block 0 zeroes A1/A3 ----------------
__global__ void kmean(const float* __restrict__ F) {
    int b = blockIdx.y, t = threadIdx.x;
    if (blockIdx.x == 0) {
        for (int i = t; i < VV * CC; i += 256) g_A1[b * VV * CC + i] = 0.f;
        if (t < VV) g_A3[b * VV + t] = 0.f;
    }
    int l0 = blockIdx.x * 128;
    const float* p = F + ((size_t)b * LL + l0) * CC + t;
    float s0 = 0.f, s1 = 0.f, s2 = 0.f, s3 = 0.f;
#pragma unroll 4
    for (int l = 0; l < 128; l += 4) {
        s0 += p[(l + 0) * CC];
        s1 += p[(l + 1) * CC];
        s2 += p[(l + 2) * CC];
        s3 += p[(l + 3) * CC];
    }
    atomicAdd(&g_base[b * CC + t], (s0 + s1) + (s2 + s3));
}

// ---------------- the big fused streaming pass ----------------
// grid (16, 32), 128 threads. Warp handles 64 tokens, 2 at a time (interleaved
// dependency chains). Lane owns columns {4L..4L+3, 128+4L..+3}.
// A1/A3 reduced in smem per block, then one global RED per element per block.
__global__ void __launch_bounds__(128) kbig(const float* __restrict__ F,
                                            float* __restrict__ attn_out,
                                            int write_attn) {
    __shared__ float sA1[VV * CC];
    __shared__ float sA3[VV];
    int b = blockIdx.y;
    int w = threadIdx.x >> 5, lane = threadIdx.x & 31;
    int l0 = blockIdx.x * 256 + w * 64;

    for (int i = threadIdx.x; i < VV * CC; i += 128) sA1[i] = 0.f;
    if (threadIdx.x < VV) sA3[threadIdx.x] = 0.f;
    __syncthreads();

    int cA = 4 * lane, cB = 128 + 4 * lane;

    float gp[VV][8], sgp[VV], sbp[VV];
#pragma unroll
    for (int v = 0; v < VV; v++) {
        sgp[v] = g_sgp[b * VV + v];
        sbp[v] = g_sbp[b * VV + v];
        const float* gpp = &g_projg[(b * VV + v) * CC];
#pragma unroll
        for (int i = 0; i < 8; i++)
            gp[v][i] = gpp[(i < 4) ? (cA + i) : (cB + (i - 4))];
    }
    float A1[VV][8], A3[VV];
#pragma unroll
    for (int v = 0; v < VV; v++) {
        A3[v] = 0.f;
#pragma unroll
        for (int i = 0; i < 8; i++) A1[v][i] = 0.f;
    }

    const float4* base = (const float4*)(F + ((size_t)b * LL + l0) * CC);
    float* aout = attn_out + ((size_t)b * LL + l0) * VV;

    for (int r = 0; r < 64; r += 2) {
        float4 fa0 = base[r * 64 + lane];
        float4 fb0 = base[r * 64 + lane + 32];
        float4 fa1 = base[r * 64 + 64 + lane];
        float4 fb1 = base[r * 64 + 96 + lane];
        float f0[8] = {fa0.x, fa0.y, fa0.z, fa0.w, fb0.x, fb0.y, fb0.z, fb0.w};
        float f1[8] = {fa1.x, fa1.y, fa1.z, fa1.w, fb1.x, fb1.y, fb1.z, fb1.w};

        float s0 = 0.f, q0 = 0.f, s1 = 0.f, q1 = 0.f;
        float d0[VV] = {0, 0, 0, 0, 0}, d1[VV] = {0, 0, 0, 0, 0};
#pragma unroll
        for (int i = 0; i < 8; i++) {
            float x0 = f0[i], x1 = f1[i];
            s0 += x0; q0 += x0 * x0;
            s1 += x1; q1 += x1 * x1;
#pragma unroll
            for (int v = 0; v < VV; v++) {
                d0[v] += x0 * gp[v][i];
                d1[v] += x1 * gp[v][i];
            }
        }
#pragma unroll
        for (int off = 16; off; off >>= 1) {
            s0 += __shfl_xor_sync(0xffffffffu, s0, off);
            s1 += __shfl_xor_sync(0xffffffffu, s1, off);
            q0 += __shfl_xor_sync(0xffffffffu, q0, off);
            q1 += __shfl_xor_sync(0xffffffffu, q1, off);
#pragma unroll
            for (int v = 0; v < VV; v++) {
                d0[v] += __shfl_xor_sync(0xffffffffu, d0[v], off);
                d1[v] += __shfl_xor_sync(0xffffffffu, d1[v], off);
            }
        }
        float m0 = s0 * (1.0f / 256.0f);
        float m1 = s1 * (1.0f / 256.0f);
        float rs0 = rsqrtf(q0 * (1.0f / 256.0f) - m0 * m0 + 1e-5f);
        float rs1 = rsqrtf(q1 * (1.0f / 256.0f) - m1 * m1 + 1e-5f);

        float lg0[VV], lg1[VV];
#pragma unroll
        for (int v = 0; v < VV; v++) {
            lg0[v] = rs0 * (d0[v] - m0 * sgp[v]) + sbp[v];
            lg1[v] = rs1 * (d1[v] - m1 * sgp[v]) + sbp[v];
        }
        float mx0 = lg0[0], mx1 = lg1[0];
#pragma unroll
        for (int v = 1; v < VV; v++) {
            mx0 = fmaxf(mx0, lg0[v]);
            mx1 = fmaxf(mx1, lg1[v]);
        }
        float e0[VV], e1[VV], se0 = 0.f, se1 = 0.f;
#pragma unroll
        for (int v = 0; v < VV; v++) {
            e0[v] = __expf(lg0[v] - mx0); se0 += e0[v];
            e1[v] = __expf(lg1[v] - mx1); se1 += e1[v];
        }
        float inv0 = 1.0f / se0, inv1 = 1.0f / se1;
        float a0[VV], a1[VV];
#pragma unroll
        for (int v = 0; v < VV; v++) {
            a0[v] = e0[v] * inv0;
            a1[v] = e1[v] * inv1;
        }

#pragma unroll
        for (int i = 0; i < 8; i++) { f0[i] -= m0; f1[i] -= m1; }
#pragma unroll
        for (int v = 0; v < VV; v++) {
            float c0 = a0[v] * rs0, c1 = a1[v] * rs1;
            A3[v] += a0[v] + a1[v];
#pragma unroll
            for (int i = 0; i < 8; i++)
                A1[v][i] += c0 * f0[i] + c1 * f1[i];
        }

        if (write_attn) {
            if (lane < VV) {
                float av = lane == 0 ? a0[0] : lane == 1 ? a0[1] : lane == 2 ? a0[2]
                         : lane == 3 ? a0[3] : a0[4];
                aout[r * VV + lane] = av;
            } else if (lane < 2 * VV) {
                int j = lane - VV;
                float av = j == 0 ? a1[0] : j == 1 ? a1[1] : j == 2 ? a1[2]
                         : j == 3 ? a1[3] : a1[4];
                aout[(r + 1) * VV + j] = av;
            }
        }
    }

#pragma unroll
    for (int v = 0; v < VV; v++) {
#pragma unroll
        for (int i = 0; i < 8; i++) {
            int c = (i < 4) ? (cA + i) : (cB + (i - 4));
            atomicAdd(&sA1[v * CC + c], A1[v][i]);
        }
        if (lane == 0) atomicAdd(&sA3[v], A3[v]);
    }
    __syncthreads();
    for (int i = threadIdx.x; i < VV * CC; i += 128)
        atomicAdd(&g_A1[b * VV * CC + i], sA1[i]);
    if (threadIdx.x < VV)
        atomicAdd(&g_A3[b * VV + threadIdx.x], sA3[threadIdx.x]);
}

// ---------------- per-batch slot update + projection for next iteration ----------------
// grid = 32 (one block per batch), 512 threads. GEMM phases k-split across
// all 512 threads with unroll-8 weight loads (MLP ~8 on L2-latency loads).
__global__ void __launch_bounds__(512) kslot(
    float* __restrict__ slots_g,             // lives in d_out
    const float* __restrict__ noise,
    const float* __restrict__ g_in_p, const float* __restrict__ b_in_p,
    const float* __restrict__ g_sl,   const float* __restrict__ b_sl,
    const float* __restrict__ g_up,   const float* __restrict__ b_up,
    const float* __restrict__ Wv,
    const float* __restrict__ W1, const float* __restrict__ b1,
    const float* __restrict__ W2, const float* __restrict__ b2,
    const float* __restrict__ scale_p, const float* __restrict__ ns_p,
    int do_init, int do_update, int do_proj)
{
    __shared__ float sSlots[VV][CC];
    __shared__ float sA[VV][CC];       // S (attn^T x) then slots_norm (reused)
    __shared__ float sU[VV][CC];
    __shared__ float sH[VV][CC];
    __shared__ float sHid[VV][2 * CC];
    __shared__ float sP[2][VV][CC];    // k-split partials
    __shared__ float a3s[VV];
    __shared__ float sred[2 * VV];

    int b = blockIdx.x, t = threadIdx.x;
    int wid = t >> 5, lane = t & 31;
    int h = t >> 8, col = t & 255;     // k-split half + output column

    if (do_init) {
        float ns = fabsf(ns_p[0]);
        for (int idx = t; idx < VV * CC; idx += 512) {
            int v = idx >> 8, c = idx & 255;
            float s = g_base[b * CC + c] * (1.0f / (float)LL)
                    + noise[(b * VV + v) * CC + c] * ns;
            sSlots[v][c] = s;
            slots_g[(b * VV + v) * CC + c] = s;
        }
    } else {
        for (int idx = t; idx < VV * CC; idx += 512) {
            int v = idx >> 8, c = idx & 255;
            sSlots[v][c] = slots_g[(b * VV + v) * CC + c];
        }
    }
    __syncthreads();

    if (do_update) {
        if (t < VV) { a3s[t] = g_A3[b * VV + t]; g_A3[b * VV + t] = 0.f; }
        __syncthreads();
        for (int idx = t; idx < VV * CC; idx += 512) {
            int v = idx >> 8, c = idx & 255;
            int gi = (b * VV + v) * CC + c;
            float a1v = g_A1[gi];
            g_A1[gi] = 0.f;
            sA[v][c] = g_in_p[c] * a1v + b_in_p[c] * a3s[v];
        }
        __syncthreads();
        {   // sU = (sA @ Wv) / asum, k-split over halves of 128
            float acc[VV] = {0.f, 0.f, 0.f, 0.f, 0.f};
            int c0 = h * 128;
#pragma unroll 8
            for (int c2 = 0; c2 < 128; c2++) {
                float wv = Wv[(c0 + c2) * CC + col];
#pragma unroll
                for (int v = 0; v < VV; v++) acc[v] += sA[v][c0 + c2] * wv;
            }
#pragma unroll
            for (int v = 0; v < VV; v++) sP[h][v][col] = acc[v];
        }
        __syncthreads();
        if (t < CC) {
#pragma unroll
            for (int v = 0; v < VV; v++)
                sU[v][t] = (sP[0][v][t] + sP[1][v][t]) / (a3s[v] + 1e-8f);
        }
        __syncthreads();
        if (wid < VV) {   // LayerNorm of updates, one warp per slot
            int v = wid;
            float uv[8], s = 0.f, s2 = 0.f;
#pragma unroll
            for (int i = 0; i < 8; i++) {
                uv[i] = sU[v][lane + 32 * i];
                s += uv[i]; s2 += uv[i] * uv[i];
            }
#pragma unroll
            for (int off = 16; off; off >>= 1) {
                s  += __shfl_xor_sync(0xffffffffu, s, off);
                s2 += __shfl_xor_sync(0xffffffffu, s2, off);
            }
            float m = s * (1.0f / 256.0f);
            float rs = rsqrtf(s2 * (1.0f / 256.0f) - m * m + 1e-5f);
#pragma unroll
            for (int i = 0; i < 8; i++) {
                int c = lane + 32 * i;
                sH[v][c] = (uv[i] - m) * rs * g_up[c] + b_up[c];
            }
        }
        __syncthreads();
        {   // hidden = relu(sH @ W1 + b1), all 512 outputs, one thread each
            float acc[VV];
            float bb = b1[t];
#pragma unroll
            for (int v = 0; v < VV; v++) acc[v] = bb;
#pragma unroll 8
            for (int c = 0; c < CC; c++) {
                float wv = W1[c * (2 * CC) + t];
#pragma unroll
                for (int v = 0; v < VV; v++) acc[v] += sH[v][c] * wv;
            }
#pragma unroll
            for (int v = 0; v < VV; v++) sHid[v][t] = fmaxf(acc[v], 0.f);
        }
        __syncthreads();
        {   // delta = sHid @ W2 + b2, k-split over halves of 256
            float acc[VV] = {0.f, 0.f, 0.f, 0.f, 0.f};
            int j0 = h * 256;
#pragma unroll 8
            for (int j = 0; j < 256; j++) {
                float wv = W2[(j0 + j) * CC + col];
#pragma unroll
                for (int v = 0; v < VV; v++) acc[v] += sHid[v][j0 + j] * wv;
            }
#pragma unroll
            for (int v = 0; v < VV; v++) sP[h][v][col] = acc[v];
        }
        __syncthreads();
        if (t < CC) {
            float bb = b2[t];
#pragma unroll
            for (int v = 0; v < VV; v++) {
                float sv = sSlots[v][t] + sP[0][v][t] + sP[1][v][t] + bb;
                sSlots[v][t] = sv;
                slots_g[(b * VV + v) * CC + t] = sv;
            }
        }
        __syncthreads();
    }

    if (do_proj) {
        if (t < 2 * VV) sred[t] = 0.f;
        if (wid < VV) {   // LN(slots) with g_slots/b_slots -> sA
            int v = wid;
            float uv[8], s = 0.f, s2 = 0.f;
#pragma unroll
            for (int i = 0; i < 8; i++) {
                uv[i] = sSlots[v][lane + 32 * i];
                s += uv[i]; s2 += uv[i] * uv[i];
            }
#pragma unroll
            for (int off = 16; off; off >>= 1) {
                s  += __shfl_xor_sync(0xffffffffu, s, off);
                s2 += __shfl_xor_sync(0xffffffffu, s2, off);
            }
            float m = s * (1.0f / 256.0f);
            float rs = rsqrtf(s2 * (1.0f / 256.0f) - m * m + 1e-5f);
#pragma unroll
            for (int i = 0; i < 8; i++) {
                int c = lane + 32 * i;
                sA[v][c] = (uv[i] - m) * rs * g_sl[c] + b_sl[c];
            }
        }
        __syncthreads();
        {   // proj[c,v] = sum_e MT[e,c]*sA[v][e], k-split halves of 128
            float acc[VV] = {0.f, 0.f, 0.f, 0.f, 0.f};
            int e0 = h * 128;
#pragma unroll 8
            for (int e = 0; e < 128; e++) {
                float mc = g_MT[(e0 + e) * CC + col];
#pragma unroll
                for (int v = 0; v < VV; v++) acc[v] += mc * sA[v][e0 + e];
            }
#pragma unroll
            for (int v = 0; v < VV; v++) sP[h][v][col] = acc[v];
        }
        __syncthreads();
        if (t < CC) {
            float sc = scale_p[0];
            float gi_c = g_in_p[t], bi_c = b_in_p[t];
            float cg[VV], cb[VV];
#pragma unroll
            for (int v = 0; v < VV; v++) {
                float pr = (sP[0][v][t] + sP[1][v][t]) * sc;
                float gpv = gi_c * pr;
                g_projg[(b * VV + v) * CC + t] = gpv;
                cg[v] = gpv;
                cb[v] = bi_c * pr;
            }
#pragma unroll
            for (int off = 16; off; off >>= 1) {
#pragma unroll
                for (int v = 0; v < VV; v++) {
                    cg[v] += __shfl_xor_sync(0xffffffffu, cg[v], off);
                    cb[v] += __shfl_xor_sync(0xffffffffu, cb[v], off);
                }
            }
            if (lane == 0) {
#pragma unroll
                for (int v = 0; v < VV; v++) {
                    atomicAdd(&sred[v], cg[v]);
                    atomicAdd(&sred[VV + v], cb[v]);
                }
            }
        }
        __syncthreads();
        if (t < VV) {
            g_sgp[b * VV + t] = sred[t];
            g_sbp[b * VV + t] = sred[VV + t];
        }
    }
}

extern "C" void kernel_launch(void* const* d_in, const int* in_sizes, int n_in,
                              void* d_out, int out_size) {
    const float* F     = (const float*)d_in[0];
    const float* noise = (const float*)d_in[1];
    const float* Wq    = (const float*)d_in[2];
    const float* Wk    = (const float*)d_in[3];
    const float* Wv    = (const float*)d_in[4];
    const float* scale = (const float*)d_in[5];
    const float* g_in  = (const float*)d_in[6];
    const float* b_in  = (const float*)d_in[7];
    const float* g_sl  = (const float*)d_in[8];
    const float* b_sl  = (const float*)d_in[9];
    const float* g_up  = (const float*)d_in[10];
    const float* b_up  = (const float*)d_in[11];
    const float* W1    = (const float*)d_in[12];
    const float* b1    = (const float*)d_in[13];
    const float* W2    = (const float*)d_in[14];
    const float* b2    = (const float*)d_in[15];
    const float* nsc   = (const float*)d_in[16];

    float* out       = (float*)d_out;
    float* slots_out = out;                     // [B,V,C] = 40960 floats
    float* attn_out  = out + BB * VV * CC;      // [B,L,V] = 655360 floats

    km<<<dim3(8, 8), 256>>>(Wq, Wk);                     // #1 (also zeroes g_base)
    kmean<<<dim3(32, 32), 256>>>(F);                     // #2 (also zeroes A1/A3)

    // iter 1: init slots + proj
    kslot<<<32, 512>>>(slots_out, noise, g_in, b_in, g_sl, b_sl, g_up, b_up,
                       Wv, W1, b1, W2, b2, scale, nsc, 1, 0, 1);   // #3
    kbig<<<dim3(16, 32), 128>>>(F, attn_out, 0);                   // #4
    // iter 2: update + proj
    kslot<<<32, 512>>>(slots_out, noise, g_in, b_in, g_sl, b_sl, g_up, b_up,
                       Wv, W1, b1, W2, b2, scale, nsc, 0, 1, 1);   // #5
    kbig<<<dim3(16, 32), 128>>>(F, attn_out, 0);                   // #6 <- profiled
    // iter 3: update + proj, last big pass writes attn
    kslot<<<32, 512>>>(slots_out, noise, g_in, b_in, g_sl, b_sl, g_up, b_up,
                       Wv, W1, b1, W2, b2, scale, nsc, 0, 1, 1);   // #7
    kbig<<<dim3(16, 32), 128>>>(F, attn_out, 1);                   // #8
    // final slot update (no proj needed)
    kslot<<<32, 512>>>(slots_out, noise, g_in, b_in, g_sl, b_sl, g_up, b_up,
                       Wv, W1, b1, W2, b2, scale, nsc, 0, 1, 0);   // #9
}

// round 4
// speedup vs baseline: 1.5253x; 1.2744x over previous
#include <cuda_runtime.h>
#include <math.h>

#define BB 32
#define LL 4096
#define CC 256
#define VV 5
#define GX 8            // kbig blocks per batch
#define THR 256
#define NSUB 8          // 512 tokens per block / 64 per subtile

// ---------------- device scratch ----------------
__device__ __align__(16) float g_base[BB * CC];
__device__ __align__(16) float g_A1[BB * VV * CC];   // sum_l w*f   (w = a*rs)
__device__ __align__(16) float g_Z[BB * VV];         // sum_l w*m
__device__ __align__(16) float g_A3[BB * VV];        // sum_l a
__device__ __align__(16) float g_projg[BB * VV * CC];
__device__ __align__(16) float g_sgp[BB * VV];
__device__ __align__(16) float g_sbp[BB * VV];
__device__ __align__(16) float g_MT[CC * CC];        // MT[e][c] = sum_k Wk[e,k]*Wq[c,k]
__device__ unsigned g_cnt[BB];

// ---------------- tail smem overlay (dynamic smem, offsets in bytes) ----------------
#define T_SL(sm)  ((float*)(sm))                 // [5][256]
#define T_X(sm)   ((float*)((sm) + 5120))        // [5][256]
#define T_U(sm)   ((float*)((sm) + 10240))       // [5][256]
#define T_H(sm)   ((float*)((sm) + 15360))       // [5][256]
#define T_HID(sm) ((float*)((sm) + 20480))       // [5][512]
#define T_P(sm)   ((float*)((sm) + 30720))       // [4][5][256] or [2][5][512]
#define T_PR(sm)  ((float*)((sm) + 51200))       // [5][256]
#define TAIL_BYTES 56320

// kbig main-phase smem layout
#define KB_SF(sm)   ((float*)(sm))               // [64][272]   69632 B
#define KB_GP(sm)   ((float*)((sm) + 69632))     // [5][256]    5120 B
#define KB_W(sm)    ((float*)((sm) + 74752))     // [64][20]    5120 B
#define KB_MISC(sm) ((float*)((sm) + 79872))     // sgp[5] sbp[5] flag
#define KB_BYTES 80000

// ---------------- helpers ----------------
__device__ __forceinline__ void ln_rows(const float* __restrict__ src,
                                        float* __restrict__ dst,
                                        const float* __restrict__ gc,
                                        const float* __restrict__ bc, int t) {
    int wid = t >> 5, lane = t & 31;
    if (wid < VV) {
        float x[8], s = 0.f, q = 0.f;
#pragma unroll
        for (int i = 0; i < 8; i++) {
            x[i] = src[wid * CC + lane + 32 * i];
            s += x[i]; q += x[i] * x[i];
        }
#pragma unroll
        for (int off = 16; off; off >>= 1) {
            s += __shfl_xor_sync(0xffffffffu, s, off);
            q += __shfl_xor_sync(0xffffffffu, q, off);
        }
        float m = s * (1.0f / 256.0f);
        float rs = rsqrtf(q * (1.0f / 256.0f) - m * m + 1e-5f);
#pragma unroll
        for (int i = 0; i < 8; i++) {
            int c = lane + 32 * i;
            dst[wid * CC + c] = (x[i] - m) * rs * gc[c] + bc[c];
        }
    }
}

// out 256 cols, depth 256, W row-major [256][256]; 4-way k-split, float4 weights
__device__ __forceinline__ void gemm256(const float* __restrict__ sIn,
                                        const float* __restrict__ W,
                                        float* __restrict__ sP, int t) {
    int grp = t & 63, seg = t >> 6;
    const float4* Wp = (const float4*)W + seg * 4096 + grp;
    const float* xin = sIn + seg * 64;
    float a0[VV], a1[VV], a2[VV], a3[VV];
#pragma unroll
    for (int v = 0; v < VV; v++) a0[v] = a1[v] = a2[v] = a3[v] = 0.f;
#pragma unroll 4
    for (int k = 0; k < 64; k++) {
        float4 w = Wp[k * 64];
#pragma unroll
        for (int v = 0; v < VV; v++) {
            float xa = xin[v * CC + k];
            a0[v] += xa * w.x; a1[v] += xa * w.y;
            a2[v] += xa * w.z; a3[v] += xa * w.w;
        }
    }
#pragma unroll
    for (int v = 0; v < VV; v++) {
        float* p = sP + ((seg * VV + v) << 8) + (grp << 2);
        p[0] = a0[v]; p[1] = a1[v]; p[2] = a2[v]; p[3] = a3[v];
    }
}

// out 512, depth 256 from sH[5][256], W1 [256][512]; 2-way k-split
__device__ __forceinline__ void gemmW1(const float* __restrict__ sH,
                                       const float* __restrict__ W1,
                                       float* __restrict__ sP, int t) {
    int grp = t & 127, seg = t >> 7;
    const float4* Wp = (const float4*)W1 + seg * 16384 + grp;
    const float* xin = sH + seg * 128;
    float a0[VV], a1[VV], a2[VV], a3[VV];
#pragma unroll
    for (int v = 0; v < VV; v++) a0[v] = a1[v] = a2[v] = a3[v] = 0.f;
#pragma unroll 4
    for (int k = 0; k < 128; k++) {
        float4 w = Wp[k * 128];
#pragma unroll
        for (int v = 0; v < VV; v++) {
            float xa = xin[v * CC + k];
            a0[v] += xa * w.x; a1[v] += xa * w.y;
            a2[v] += xa * w.z; a3[v] += xa * w.w;
        }
    }
#pragma unroll
    for (int v = 0; v < VV; v++) {
        float* p = sP + ((seg * VV + v) << 9) + (grp << 2);
        p[0] = a0[v]; p[1] = a1[v]; p[2] = a2[v]; p[3] = a3[v];
    }
}

// out 256, depth 512 from sHid[5][512], W2 [512][256]; 4-way k-split
__device__ __forceinline__ void gemmW2(const float* __restrict__ sHid,
                                       const float* __restrict__ W2,
                                       float* __restrict__ sP, int t) {
    int grp = t & 63, seg = t >> 6;
    const float4* Wp = (const float4*)W2 + seg * 8192 + grp;
    const float* xin = sHid + seg * 128;
    float a0[VV], a1[VV], a2[VV], a3[VV];
#pragma unroll
    for (int v = 0; v < VV; v++) a0[v] = a1[v] = a2[v] = a3[v] = 0.f;
#pragma unroll 4
    for (int k = 0; k < 128; k++) {
        float4 w = Wp[k * 64];
#pragma unroll
        for (int v = 0; v < VV; v++) {
            float xa = xin[v * 512 + k];
            a0[v] += xa * w.x; a1[v] += xa * w.y;
            a2[v] += xa * w.z; a3[v] += xa * w.w;
        }
    }
#pragma unroll
    for (int v = 0; v < VV; v++) {
        float* p = sP + ((seg * VV + v) << 8) + (grp << 2);
        p[0] = a0[v]; p[1] = a1[v]; p[2] = a2[v]; p[3] = a3[v];
    }
}

// LN(slots) -> proj for next iteration. Requires T_SL filled. 256 threads.
__device__ void ln_proj_tail(char* sm, int t, int b,
                             const float* g_sl, const float* b_sl,
                             const float* g_in, const float* b_in, float scale) {
    float* sSl = T_SL(sm); float* sX = T_X(sm);
    float* sP = T_P(sm);   float* sPR = T_PR(sm);
    ln_rows(sSl, sX, g_sl, b_sl, t);
    __syncthreads();
    gemm256(sX, g_MT, sP, t);
    __syncthreads();
    for (int idx = t; idx < VV * CC; idx += THR) {
        int v = idx >> 8, c = idx & 255;
        float pr = (sP[(v << 8) + c] + sP[((VV + v) << 8) + c] +
                    sP[((2 * VV + v) << 8) + c] + sP[((3 * VV + v) << 8) + c]) * scale;
        g_projg[b * VV * CC + idx] = g_in[c] * pr;
        sPR[idx] = pr;
    }
    __syncthreads();
    if (t < 10) {
        int v = t % 5;
        const float* coef = (t < 5) ? g_in : b_in;
        float s = 0.f;
#pragma unroll 8
        for (int c = 0; c < CC; c++) s += coef[c] * sPR[v * CC + c];
        if (t < 5) g_sgp[b * VV + v] = s; else g_sbp[b * VV + v] = s;
    }
}

// Full slot update (reads g_A1/g_Z/g_A3, zeroes them), writes slots, optional proj.
__device__ void update_tail(char* sm, int t, int b, float* slots,
                            const float* g_in, const float* b_in,
                            const float* g_sl, const float* b_sl,
                            const float* g_up, const float* b_up,
                            const float* Wv, const float* W1, const float* b1,
                            const float* W2, const float* b2,
                            float scale, int do_proj) {
    __shared__ float s_a3[VV], s_z[VV];
    float* sSl = T_SL(sm); float* sX = T_X(sm); float* sU = T_U(sm);
    float* sH = T_H(sm);   float* sHid = T_HID(sm); float* sP = T_P(sm);

    if (t < VV) {
        s_a3[t] = __ldcg(&g_A3[b * VV + t]); g_A3[b * VV + t] = 0.f;
        s_z[t]  = __ldcg(&g_Z[b * VV + t]);  g_Z[b * VV + t] = 0.f;
    }
    for (int idx = t; idx < VV * CC; idx += THR)
        sSl[idx] = slots[b * VV * CC + idx];
    __syncthreads();
    for (int idx = t; idx < VV * CC; idx += THR) {
        int v = idx >> 8, c = idx & 255;
        float a1 = __ldcg(&g_A1[b * VV * CC + idx]) - s_z[v];
        g_A1[b * VV * CC + idx] = 0.f;
        sX[idx] = g_in[c] * a1 + b_in[c] * s_a3[v];
    }
    __syncthreads();
    gemm256(sX, Wv, sP, t);
    __syncthreads();
    for (int idx = t; idx < VV * CC; idx += THR) {
        int v = idx >> 8, c = idx & 255;
        sU[idx] = (sP[(v << 8) + c] + sP[((VV + v) << 8) + c] +
                   sP[((2 * VV + v) << 8) + c] + sP[((3 * VV + v) << 8) + c])
                  / (s_a3[v] + 1e-8f);
    }
    __syncthreads();
    ln_rows(sU, sH, g_up, b_up, t);
    __syncthreads();
    gemmW1(sH, W1, sP, t);
    __syncthreads();
    for (int idx = t; idx < VV * 512; idx += THR) {
        int v = idx >> 9, j = idx & 511;
        float h = sP[(v << 9) + j] + sP[((VV + v) << 9) + j] + b1[j];
        sHid[idx] = fmaxf(h, 0.f);
    }
    __syncthreads();
    gemmW2(sHid, W2, sP, t);
    __syncthreads();
    for (int idx = t; idx < VV * CC; idx += THR) {
        int v = idx >> 8, c = idx & 255;
        float d = sP[(v << 8) + c] + sP[((VV + v) << 8) + c] +
                  sP[((2 * VV + v) << 8) + c] + sP[((3 * VV + v) << 8) + c] + b2[c];
        float sn = sSl[idx] + d;
        sSl[idx] = sn;
        slots[b * VV * CC + idx] = sn;
    }
    __syncthreads();
    if (do_proj)
        ln_proj_tail(sm, t, b, g_sl, b_sl, g_in, b_in, scale);
    if (t == 0) g_cnt[b] = 0;
}

// ---------------- km: MT = Wk @ Wq^T + zero all scratch ----------------
__global__ void __launch_bounds__(256) km(const float* __restrict__ Wq,
                                          const float* __restrict__ Wk) {
    __shared__ float As[32][33];
    __shared__ float Bs[32][33];
    int tx = threadIdx.x & 31, ty = threadIdx.x >> 5;
    int c0 = blockIdx.x * 32, e0 = blockIdx.y * 32;

    int flat = (blockIdx.y * 8 + blockIdx.x) * 256 + threadIdx.x;  // 0..16383
    for (int i = flat; i < BB * VV * CC; i += 16384) g_A1[i] = 0.f;
    if (flat < BB * CC) g_base[flat] = 0.f;
    if (flat < BB * VV) { g_Z[flat] = 0.f; g_A3[flat] = 0.f; }
    if (flat < BB) g_cnt[flat] = 0u;

    float acc[4] = {0.f, 0.f, 0.f, 0.f};
    for (int k0 = 0; k0 < CC; k0 += 32) {
#pragma unroll
        for (int j = 0; j < 4; j++) {
            As[ty + 8 * j][tx] = Wk[(e0 + ty + 8 * j) * CC + k0 + tx];
            Bs[ty + 8 * j][tx] = Wq[(c0 + ty + 8 * j) * CC + k0 + tx];
        }
        __syncthreads();
#pragma unroll
        for (int kk = 0; kk < 32; kk++) {
            float bq = Bs[tx][kk];
#pragma unroll
            for (int j = 0; j < 4; j++) acc[j] += As[ty + 8 * j][kk] * bq;
        }
        __syncthreads();
    }
#pragma unroll
    for (int j = 0; j < 4; j++)
        g_MT[(e0 + ty + 8 * j) * CC + c0 + tx] = acc[j];
}

// ---------------- kmean: feature mean; last block per batch does slots init + proj ----------------
__global__ void __launch_bounds__(256) kmean(const float* __restrict__ F,
                                             const float* __restrict__ noise,
                                             float* __restrict__ slots,
                                             const float* __restrict__ g_in,
                                             const float* __restrict__ b_in,
                                             const float* __restrict__ g_sl,
                                             const float* __restrict__ b_sl,
                                             const float* __restrict__ scale_p,
                                             const float* __restrict__ ns_p) {
    extern __shared__ char sm[];
    __shared__ unsigned flg;
    int b = blockIdx.y, t = threadIdx.x;
    const float* p = F + ((size_t)b * LL + blockIdx.x * 128) * CC + t;
    float s = 0.f;
#pragma unroll 8
    for (int l = 0; l < 128; l++) s += p[l * CC];
    atomicAdd(&g_base[b * CC + t], s);
    __threadfence();
    if (t == 0) flg = atomicAdd(&g_cnt[b], 1u);
    __syncthreads();
    if (flg != 31u) return;

    // init slots = mean + noise*|ns|
    float* sSl = T_SL(sm);
    float ns = fabsf(ns_p[0]);
    for (int idx = t; idx < VV * CC; idx += THR) {
        int c = idx & 255;
        float sv = __ldcg(&g_base[b * CC + c]) * (1.0f / (float)LL)
                 + noise[b * VV * CC + idx] * ns;
        sSl[idx] = sv;
        slots[b * VV * CC + idx] = sv;
    }
    __syncthreads();
    ln_proj_tail(sm, t, b, g_sl, b_sl, g_in, b_in, scale_p[0]);
    if (t == 0) g_cnt[b] = 0;
}

// ---------------- kbig: streaming pass; last block per batch runs slot update ----------------
__global__ void __launch_bounds__(256) kbig(const float* __restrict__ F,
                                            float* __restrict__ attn,
                                            float* __restrict__ slots,
                                            const float* __restrict__ Wv,
                                            const float* __restrict__ W1,
                                            const float* __restrict__ b1,
                                            const float* __restrict__ W2,
                                            const float* __restrict__ b2,
                                            const float* __restrict__ g_in,
                                            const float* __restrict__ b_in,
                                            const float* __restrict__ g_sl,
                                            const float* __restrict__ b_sl,
                                            const float* __restrict__ g_up,
                                            const float* __restrict__ b_up,
                                            const float* __restrict__ scale_p,
                                            int write_attn, int do_proj) {
    extern __shared__ char sm[];
    float*  sF  = KB_SF(sm);
    float4* sF4 = (float4*)sm;
    float*  sGP = KB_GP(sm);
    float*  sW  = KB_W(sm);
    float*  sMisc = KB_MISC(sm);

    int b = blockIdx.y, t = threadIdx.x;

    // preload projection (5x256) + scalars
    {
        float4* d = (float4*)sGP;
        const float4* s4 = (const float4*)(g_projg + b * VV * CC);
        for (int i = t; i < 320; i += THR) d[i] = s4[i];
        if (t < VV) { sMisc[t] = g_sgp[b * VV + t]; sMisc[VV + t] = g_sbp[b * VV + t]; }
    }
    __syncthreads();
    float sgp[VV], sbp[VV];
#pragma unroll
    for (int v = 0; v < VV; v++) { sgp[v] = sMisc[v]; sbp[v] = sMisc[VV + v]; }

    float A1r[VV] = {0.f, 0.f, 0.f, 0.f, 0.f};
    float zr = 0.f, a3r = 0.f;
    int tok = t >> 2, sub = t & 3;
    const float4* gp4 = (const float4*)sGP;

    for (int st = 0; st < NSUB; st++) {
        int l0 = blockIdx.x * 512 + st * 64;
        // load 64x256 tile (thread: row=tok, chunks sub+4i)
        {
            const float4* src = (const float4*)(F + ((size_t)(b * LL + l0 + tok)) * CC);
#pragma unroll
            for (int i = 0; i < 16; i++)
                sF4[tok * 68 + sub + 4 * i] = src[sub + 4 * i];
        }
        __syncthreads();
        // phase A: stats + logits + softmax (4 threads per token)
        {
            float s = 0.f, q = 0.f;
            float d0 = 0.f, d1 = 0.f, d2 = 0.f, d3 = 0.f, d4 = 0.f;
            const float4* fr = sF4 + tok * 68;
#pragma unroll
            for (int i = 0; i < 16; i++) {
                int ch = sub + 4 * i;
                float4 f = fr[ch];
                float4 p0 = gp4[ch], p1 = gp4[64 + ch], p2 = gp4[128 + ch];
                float4 p3 = gp4[192 + ch], p4 = gp4[256 + ch];
                s += (f.x + f.y) + (f.z + f.w);
                q += f.x * f.x + f.y * f.y + f.z * f.z + f.w * f.w;
                d0 += f.x * p0.x + f.y * p0.y + f.z * p0.z + f.w * p0.w;
                d1 += f.x * p1.x + f.y * p1.y + f.z * p1.z + f.w * p1.w;
                d2 += f.x * p2.x + f.y * p2.y + f.z * p2.z + f.w * p2.w;
                d3 += f.x * p3.x + f.y * p3.y + f.z * p3.z + f.w * p3.w;
                d4 += f.x * p4.x + f.y * p4.y + f.z * p4.z + f.w * p4.w;
            }
#pragma unroll
            for (int off = 1; off <= 2; off <<= 1) {
                s  += __shfl_xor_sync(0xffffffffu, s, off);
                q  += __shfl_xor_sync(0xffffffffu, q, off);
                d0 += __shfl_xor_sync(0xffffffffu, d0, off);
                d1 += __shfl_xor_sync(0xffffffffu, d1, off);
                d2 += __shfl_xor_sync(0xffffffffu, d2, off);
                d3 += __shfl_xor_sync(0xffffffffu, d3, off);
                d4 += __shfl_xor_sync(0xffffffffu, d4, off);
            }
            float m = s * (1.0f / 256.0f);
            float rs = rsqrtf(q * (1.0f / 256.0f) - m * m + 1e-5f);
            float lg[VV];
            lg[0] = rs * (d0 - m * sgp[0]) + sbp[0];
            lg[1] = rs * (d1 - m * sgp[1]) + sbp[1];
            lg[2] = rs * (d2 - m * sgp[2]) + sbp[2];
            lg[3] = rs * (d3 - m * sgp[3]) + sbp[3];
            lg[4] = rs * (d4 - m * sgp[4]) + sbp[4];
            float mx = fmaxf(fmaxf(fmaxf(lg[0], lg[1]), fmaxf(lg[2], lg[3])), lg[4]);
            float e[VV], se = 0.f;
#pragma unroll
            for (int v = 0; v < VV; v++) { e[v] = __expf(lg[v] - mx); se += e[v]; }
            float inv = 1.0f / se;
            if (sub == 0) {
                float* wr = sW + tok * 20;
#pragma unroll
                for (int v = 0; v < VV; v++) {
                    float a = e[v] * inv;
                    wr[v] = a * rs;
                    wr[5 + v] = a * rs * m;
                    wr[10 + v] = a;
                }
            }
        }
        __syncthreads();
        // phase B: per-column rank-5 accumulation
        {
            const float* fcol = sF + t;
#pragma unroll 4
            for (int tk = 0; tk < 64; tk++) {
                float fv = fcol[tk * 272];
                const float* wr = sW + tk * 20;
                float4 w4 = *(const float4*)wr;
                float w4b = wr[4];
                A1r[0] += w4.x * fv; A1r[1] += w4.y * fv;
                A1r[2] += w4.z * fv; A1r[3] += w4.w * fv;
                A1r[4] += w4b * fv;
            }
            if (t < VV) {
                float zz = 0.f;
#pragma unroll 8
                for (int tk = 0; tk < 64; tk++) zz += sW[tk * 20 + 5 + t];
                zr += zz;
            } else if (t >= 8 && t < 8 + VV) {
                int v = t - 8;
                float aa = 0.f;
#pragma unroll 8
                for (int tk = 0; tk < 64; tk++) aa += sW[tk * 20 + 10 + v];
                a3r += aa;
            }
            if (write_attn) {
                for (int i = t; i < 64 * VV; i += THR)
                    attn[((size_t)b * LL + l0) * VV + i] = sW[(i / 5) * 20 + 10 + (i % 5)];
            }
        }
        __syncthreads();
    }

    // flush block contributions
#pragma unroll
    for (int v = 0; v < VV; v++)
        atomicAdd(&g_A1[b * VV * CC + v * CC + t], A1r[v]);
    if (t < VV) atomicAdd(&g_Z[b * VV + t], zr);
    else if (t >= 8 && t < 8 + VV) atomicAdd(&g_A3[b * VV + (t - 8)], a3r);
    __threadfence();
    unsigned* flagp = (unsigned*)(sMisc + 10);
    if (t == 0) *flagp = atomicAdd(&g_cnt[b], 1u);
    __syncthreads();
    if (*flagp != GX - 1) return;

    update_tail(sm, t, b, slots, g_in, b_in, g_sl, b_sl, g_up, b_up,
                Wv, W1, b1, W2, b2, scale_p[0], do_proj);
}

// ---------------- host ----------------
extern "C" void kernel_launch(void* const* d_in, const int* in_sizes, int n_in,
                              void* d_out, int out_size) {
    const float* F     = (const float*)d_in[0];
    const float* noise = (const float*)d_in[1];
    const float* Wq    = (const float*)d_in[2];
    const float* Wk    = (const float*)d_in[3];
    const float* Wv    = (const float*)d_in[4];
    const float* scale = (const float*)d_in[5];
    const float* g_in  = (const float*)d_in[6];
    const float* b_in  = (const float*)d_in[7];
    const float* g_sl  = (const float*)d_in[8];
    const float* b_sl  = (const float*)d_in[9];
    const float* g_up  = (const float*)d_in[10];
    const float* b_up  = (const float*)d_in[11];
    const float* W1    = (const float*)d_in[12];
    const float* b1    = (const float*)d_in[13];
    const float* W2    = (const float*)d_in[14];
    const float* b2    = (const float*)d_in[15];
    const float* nsc   = (const float*)d_in[16];

    float* out       = (float*)d_out;
    float* slots_out = out;                    // [B,V,C]
    float* attn_out  = out + BB * VV * CC;     // [B,L,V]

    cudaFuncSetAttribute(kmean, cudaFuncAttributeMaxDynamicSharedMemorySize, TAIL_BYTES);
    cudaFuncSetAttribute(kbig,  cudaFuncAttributeMaxDynamicSharedMemorySize, KB_BYTES);

    km<<<dim3(8, 8), 256>>>(Wq, Wk);
    kmean<<<dim3(32, 32), 256, TAIL_BYTES>>>(F, noise, slots_out, g_in, b_in,
                                             g_sl, b_sl, scale, nsc);
    kbig<<<dim3(GX, 32), 256, KB_BYTES>>>(F, attn_out, slots_out, Wv, W1, b1, W2, b2,
                                          g_in, b_in, g_sl, b_sl, g_up, b_up, scale,
                                          0, 1);
    kbig<<<dim3(GX, 32), 256, KB_BYTES>>>(F, attn_out, slots_out, Wv, W1, b1, W2, b2,
                                          g_in, b_in, g_sl, b_sl, g_up, b_up, scale,
                                          0, 1);
    kbig<<<dim3(GX, 32), 256, KB_BYTES>>>(F, attn_out, slots_out, Wv, W1, b1, W2, b2,
                                          g_in, b_in, g_sl, b_sl, g_up, b_up, scale,
                                          1, 0);
}